// round 3
// baseline (speedup 1.0000x reference)
#include <cuda_runtime.h>
#include <cstdint>

// ---------------------------------------------------------------------------
// CrossAttention: x_l/x_g [4,512,32,32]; six 3x3 convs -> heads(spatial split)
// -> cross attention (S=512 channels, d=128 spatial chunk) -> 1x1 proj -> res.
// fp32 throughout. GEMM core: 128x128 block tile, 8x8 per thread, fma.rn.f32x2.
// ---------------------------------------------------------------------------

#define NB   4
#define CCH  512
#define HW   1024          // 32*32
#define NHD  8
#define DHEAD 128          // HW / NH

// Scratch (no allocations allowed -> __device__ globals)
__device__ float g_wt[6][9 * 512 * 512];        // [r][ci][co]
__device__ float g_wpt[2][512 * 512];           // [ci][co]
__device__ float g_qkv[6][NB * CCH * HW];       // kl,ql,vl,kg,qg,vg
__device__ float g_att[2][NB * NHD * 512 * 512];// att_g, att_l
__device__ float g_y[2][NB * CCH * HW];         // y_g, y_l

// ----------------------------- f32x2 helpers -------------------------------
__device__ __forceinline__ unsigned long long pack2(float x, float y) {
    unsigned long long r;
    asm("mov.b64 %0, {%1, %2};" : "=l"(r) : "f"(x), "f"(y));
    return r;
}
__device__ __forceinline__ unsigned long long ffma2(unsigned long long a,
                                                    unsigned long long b,
                                                    unsigned long long c) {
    unsigned long long d;
    asm("fma.rn.f32x2 %0, %1, %2, %3;" : "=l"(d) : "l"(a), "l"(b), "l"(c));
    return d;
}
__device__ __forceinline__ void unpack2(unsigned long long v, float& x, float& y) {
    asm("mov.b64 {%0, %1}, %2;" : "=f"(x), "=f"(y) : "l"(v));
}

// ------------------------- shared GEMM inner core ---------------------------
// As/Bs: [16][132] (K-chunk x 128 + pad). Thread (ty,tx) computes rows
// m = ty*8..+7, cols n = tx*8..+7 via f32x2 pairs.
#define SMPAD 132

__device__ __forceinline__ void mma_chunk(const float (*As)[SMPAD],
                                          const float (*Bs)[SMPAD],
                                          int ty, int tx,
                                          unsigned long long acc[8][4]) {
#pragma unroll
    for (int k = 0; k < 16; ++k) {
        float4 a0 = *(const float4*)&As[k][ty * 8];
        float4 a1 = *(const float4*)&As[k][ty * 8 + 4];
        float4 b0 = *(const float4*)&Bs[k][tx * 8];
        float4 b1 = *(const float4*)&Bs[k][tx * 8 + 4];
        unsigned long long bp[4];
        bp[0] = pack2(b0.x, b0.y);
        bp[1] = pack2(b0.z, b0.w);
        bp[2] = pack2(b1.x, b1.y);
        bp[3] = pack2(b1.z, b1.w);
        float av[8] = {a0.x, a0.y, a0.z, a0.w, a1.x, a1.y, a1.z, a1.w};
#pragma unroll
        for (int i = 0; i < 8; ++i) {
            unsigned long long ad = pack2(av[i], av[i]);
#pragma unroll
            for (int j = 0; j < 4; ++j) acc[i][j] = ffma2(ad, bp[j], acc[i][j]);
        }
    }
}

// --------------------------- weight transposes ------------------------------
__global__ void transpose_w3(const float* __restrict__ w, float* __restrict__ wt) {
    int idx = blockIdx.x * 256 + threadIdx.x;   // 512*512*9 elements
    if (idx < 512 * 512 * 9) {
        int r  = idx % 9;
        int ci = (idx / 9) & 511;
        int co = idx / (9 * 512);
        wt[(r * 512 + ci) * 512 + co] = w[idx];
    }
}
__global__ void transpose_w1(const float* __restrict__ w, float* __restrict__ wt) {
    int idx = blockIdx.x * 256 + threadIdx.x;   // 512*512
    int ci = idx & 511;
    int co = idx >> 9;
    wt[ci * 512 + co] = w[idx];
}

// ------------------------------- conv 3x3 -----------------------------------
// grid (8 spatial-tiles, 4 co-tiles, 4 n), 256 threads.
__global__ __launch_bounds__(256, 2)
void conv3x3_kernel(const float* __restrict__ x, const float* __restrict__ wt,
                    float* __restrict__ out) {
    __shared__ float As[16][SMPAD];
    __shared__ float Bs[16][SMPAD];
    int s0 = blockIdx.x * 128, c0 = blockIdx.y * 128, n = blockIdx.z;
    int tid = threadIdx.x, tx = tid & 15, ty = tid >> 4;
    unsigned long long acc[8][4];
#pragma unroll
    for (int i = 0; i < 8; ++i)
#pragma unroll
        for (int j = 0; j < 4; ++j) acc[i][j] = 0ULL;

    const float* xb = x + (size_t)n * (CCH * HW);
    for (int r = 0; r < 9; ++r) {
        int dy = r / 3 - 1, dx = r % 3 - 1;
        const float* wr = wt + (size_t)r * 512 * 512;
        for (int c = 0; c < 512; c += 16) {
#pragma unroll
            for (int i = 0; i < 8; ++i) {
                int e = tid + i * 256;
                int kk = e >> 7, cc = e & 127;
                As[kk][cc] = wr[(size_t)(c + kk) * 512 + c0 + cc];
                int s = s0 + cc;
                int yy = (s >> 5) + dy, xx = (s & 31) + dx;
                Bs[kk][cc] = ((unsigned)yy < 32u && (unsigned)xx < 32u)
                                 ? xb[(size_t)(c + kk) * HW + yy * 32 + xx] : 0.f;
            }
            __syncthreads();
            mma_chunk(As, Bs, ty, tx, acc);
            __syncthreads();
        }
    }
#pragma unroll
    for (int i = 0; i < 8; ++i) {
        float o[8];
        unpack2(acc[i][0], o[0], o[1]);
        unpack2(acc[i][1], o[2], o[3]);
        unpack2(acc[i][2], o[4], o[5]);
        unpack2(acc[i][3], o[6], o[7]);
        float* dst = out + ((size_t)n * CCH + c0 + ty * 8 + i) * HW + s0 + tx * 8;
        *(float4*)(dst)     = make_float4(o[0], o[1], o[2], o[3]);
        *(float4*)(dst + 4) = make_float4(o[4], o[5], o[6], o[7]);
    }
}

// --------------------------------- QK^T -------------------------------------
// grid (4 ck-tiles, 4 cq-tiles, 32 n*h)
__global__ __launch_bounds__(256, 2)
void qk_kernel(const float* __restrict__ q, const float* __restrict__ k,
               float* __restrict__ att) {
    __shared__ float As[16][SMPAD];
    __shared__ float Bs[16][SMPAD];
    int nh = blockIdx.z, n = nh >> 3, h = nh & 7;
    int ck0 = blockIdx.x * 128, cq0 = blockIdx.y * 128;
    int tid = threadIdx.x, tx = tid & 15, ty = tid >> 4;
    const float* qb = q + (size_t)n * (CCH * HW) + h * DHEAD;
    const float* kb = k + (size_t)n * (CCH * HW) + h * DHEAD;
    unsigned long long acc[8][4];
#pragma unroll
    for (int i = 0; i < 8; ++i)
#pragma unroll
        for (int j = 0; j < 4; ++j) acc[i][j] = 0ULL;

    for (int d0 = 0; d0 < DHEAD; d0 += 16) {
#pragma unroll
        for (int i = 0; i < 8; ++i) {
            int e = tid + i * 256;
            int cc = e >> 4, kk = e & 15;     // transpose-on-fill
            As[kk][cc] = qb[(size_t)(cq0 + cc) * HW + d0 + kk];
            Bs[kk][cc] = kb[(size_t)(ck0 + cc) * HW + d0 + kk];
        }
        __syncthreads();
        mma_chunk(As, Bs, ty, tx, acc);
        __syncthreads();
    }
    const float SC = 0.08838834764831845f;    // 1/sqrt(128)
    float* ab = att + ((size_t)(n * NHD + h) * 512);
#pragma unroll
    for (int i = 0; i < 8; ++i) {
        float o[8];
        unpack2(acc[i][0], o[0], o[1]);
        unpack2(acc[i][1], o[2], o[3]);
        unpack2(acc[i][2], o[4], o[5]);
        unpack2(acc[i][3], o[6], o[7]);
        float* dst = att + ((size_t)(n * NHD + h) * 512 + cq0 + ty * 8 + i) * 512
                         + ck0 + tx * 8;
        *(float4*)(dst)     = make_float4(o[0]*SC, o[1]*SC, o[2]*SC, o[3]*SC);
        *(float4*)(dst + 4) = make_float4(o[4]*SC, o[5]*SC, o[6]*SC, o[7]*SC);
    }
    (void)ab;
}

// ------------------------------- softmax ------------------------------------
// one warp per 512-length row; 2048 blocks x 256 threads cover 16384 rows
__global__ void softmax_kernel(float* __restrict__ att) {
    int row  = blockIdx.x * 8 + (threadIdx.x >> 5);
    int lane = threadIdx.x & 31;
    float* p = att + (size_t)row * 512;
    float v[16];
    float m = -1e30f;
#pragma unroll
    for (int i = 0; i < 16; ++i) { v[i] = p[lane + i * 32]; m = fmaxf(m, v[i]); }
#pragma unroll
    for (int o = 16; o; o >>= 1) m = fmaxf(m, __shfl_xor_sync(0xffffffffu, m, o));
    float s = 0.f;
#pragma unroll
    for (int i = 0; i < 16; ++i) { v[i] = __expf(v[i] - m); s += v[i]; }
#pragma unroll
    for (int o = 16; o; o >>= 1) s += __shfl_xor_sync(0xffffffffu, s, o);
    float inv = 1.f / s;
#pragma unroll
    for (int i = 0; i < 16; ++i) p[lane + i * 32] = v[i] * inv;
}

// --------------------------------- A @ V ------------------------------------
// grid (4 cq-tiles, 32 n*h); N-dim = d (128)
__global__ __launch_bounds__(256, 2)
void av_kernel(const float* __restrict__ att, const float* __restrict__ v,
               float* __restrict__ y) {
    __shared__ float As[16][SMPAD];
    __shared__ float Bs[16][SMPAD];
    int nh = blockIdx.y, n = nh >> 3, h = nh & 7;
    int cq0 = blockIdx.x * 128;
    int tid = threadIdx.x, tx = tid & 15, ty = tid >> 4;
    const float* ab = att + (size_t)(n * NHD + h) * 512 * 512;
    const float* vb = v + (size_t)n * (CCH * HW) + h * DHEAD;
    unsigned long long acc[8][4];
#pragma unroll
    for (int i = 0; i < 8; ++i)
#pragma unroll
        for (int j = 0; j < 4; ++j) acc[i][j] = 0ULL;

    for (int ck = 0; ck < 512; ck += 16) {
#pragma unroll
        for (int i = 0; i < 8; ++i) {
            int e = tid + i * 256;
            int cc = e >> 4, kk = e & 15;     // att: transpose-on-fill
            As[kk][cc] = ab[(size_t)(cq0 + cc) * 512 + ck + kk];
            int k2 = e >> 7, dd = e & 127;    // v: natural fill
            Bs[k2][dd] = vb[(size_t)(ck + k2) * HW + dd];
        }
        __syncthreads();
        mma_chunk(As, Bs, ty, tx, acc);
        __syncthreads();
    }
#pragma unroll
    for (int i = 0; i < 8; ++i) {
        float o[8];
        unpack2(acc[i][0], o[0], o[1]);
        unpack2(acc[i][1], o[2], o[3]);
        unpack2(acc[i][2], o[4], o[5]);
        unpack2(acc[i][3], o[6], o[7]);
        float* dst = y + ((size_t)n * CCH + cq0 + ty * 8 + i) * HW + h * DHEAD + tx * 8;
        *(float4*)(dst)     = make_float4(o[0], o[1], o[2], o[3]);
        *(float4*)(dst + 4) = make_float4(o[4], o[5], o[6], o[7]);
    }
}

// ------------------------- 1x1 projection + residual ------------------------
// grid (8 spatial, 4 co-tiles, 4 n)
__global__ __launch_bounds__(256, 2)
void proj_kernel(const float* __restrict__ y, const float* __restrict__ wpt,
                 const float* __restrict__ xres, const float* __restrict__ rwp,
                 float* __restrict__ out) {
    __shared__ float As[16][SMPAD];
    __shared__ float Bs[16][SMPAD];
    int s0 = blockIdx.x * 128, c0 = blockIdx.y * 128, n = blockIdx.z;
    int tid = threadIdx.x, tx = tid & 15, ty = tid >> 4;
    const float* yb = y + (size_t)n * (CCH * HW);
    unsigned long long acc[8][4];
#pragma unroll
    for (int i = 0; i < 8; ++i)
#pragma unroll
        for (int j = 0; j < 4; ++j) acc[i][j] = 0ULL;

    for (int c = 0; c < 512; c += 16) {
#pragma unroll
        for (int i = 0; i < 8; ++i) {
            int e = tid + i * 256;
            int kk = e >> 7, cc = e & 127;
            As[kk][cc] = wpt[(size_t)(c + kk) * 512 + c0 + cc];
            Bs[kk][cc] = yb[(size_t)(c + kk) * HW + s0 + cc];
        }
        __syncthreads();
        mma_chunk(As, Bs, ty, tx, acc);
        __syncthreads();
    }
    float rw = *rwp;
#pragma unroll
    for (int i = 0; i < 8; ++i) {
        float o[8];
        unpack2(acc[i][0], o[0], o[1]);
        unpack2(acc[i][1], o[2], o[3]);
        unpack2(acc[i][2], o[4], o[5]);
        unpack2(acc[i][3], o[6], o[7]);
        size_t base = ((size_t)n * CCH + c0 + ty * 8 + i) * HW + s0 + tx * 8;
        float4 x0 = *(const float4*)(xres + base);
        float4 x1 = *(const float4*)(xres + base + 4);
        *(float4*)(out + base) =
            make_float4(x0.x + rw * o[0], x0.y + rw * o[1],
                        x0.z + rw * o[2], x0.w + rw * o[3]);
        *(float4*)(out + base + 4) =
            make_float4(x1.x + rw * o[4], x1.y + rw * o[5],
                        x1.z + rw * o[6], x1.w + rw * o[7]);
    }
}

// ------------------------------- launcher -----------------------------------
extern "C" void kernel_launch(void* const* d_in, const int* in_sizes, int n_in,
                              void* d_out, int out_size) {
    (void)in_sizes; (void)n_in; (void)out_size;
    const float* x_l = (const float*)d_in[0];
    const float* x_g = (const float*)d_in[1];
    const float* W3[6] = {(const float*)d_in[2], (const float*)d_in[3],
                          (const float*)d_in[4], (const float*)d_in[5],
                          (const float*)d_in[6], (const float*)d_in[7]};
    const float* Wp1 = (const float*)d_in[8];
    const float* Wp2 = (const float*)d_in[9];
    const float* rw  = (const float*)d_in[10];
    float* out_l = (float*)d_out;
    float* out_g = out_l + (size_t)NB * CCH * HW;

    void* p;
    cudaGetSymbolAddress(&p, g_wt);   float* wt   = (float*)p;
    cudaGetSymbolAddress(&p, g_wpt);  float* wpt  = (float*)p;
    cudaGetSymbolAddress(&p, g_qkv);  float* qkv  = (float*)p;
    cudaGetSymbolAddress(&p, g_att);  float* attp = (float*)p;
    cudaGetSymbolAddress(&p, g_y);    float* yb   = (float*)p;

    const size_t WT_N  = (size_t)9 * 512 * 512;
    const size_t QKV_N = (size_t)NB * CCH * HW;
    const size_t ATT_N = (size_t)NB * NHD * 512 * 512;

    for (int i = 0; i < 6; ++i)
        transpose_w3<<<9216, 256>>>(W3[i], wt + i * WT_N);
    transpose_w1<<<1024, 256>>>(Wp1, wpt);
    transpose_w1<<<1024, 256>>>(Wp2, wpt + 512 * 512);

    dim3 gconv(8, 4, 4);
    // buffers: 0 kl, 1 ql, 2 vl, 3 kg, 4 qg, 5 vg
    conv3x3_kernel<<<gconv, 256>>>(x_l, wt + 0 * WT_N, qkv + 0 * QKV_N);
    conv3x3_kernel<<<gconv, 256>>>(x_l, wt + 1 * WT_N, qkv + 1 * QKV_N);
    conv3x3_kernel<<<gconv, 256>>>(x_l, wt + 2 * WT_N, qkv + 2 * QKV_N);
    conv3x3_kernel<<<gconv, 256>>>(x_g, wt + 3 * WT_N, qkv + 3 * QKV_N);
    conv3x3_kernel<<<gconv, 256>>>(x_g, wt + 4 * WT_N, qkv + 4 * QKV_N);
    conv3x3_kernel<<<gconv, 256>>>(x_g, wt + 5 * WT_N, qkv + 5 * QKV_N);

    dim3 gqk(4, 4, 32);
    qk_kernel<<<gqk, 256>>>(qkv + 4 * QKV_N, qkv + 0 * QKV_N, attp);          // q_g, k_l
    qk_kernel<<<gqk, 256>>>(qkv + 1 * QKV_N, qkv + 3 * QKV_N, attp + ATT_N);  // q_l, k_g

    softmax_kernel<<<2048, 256>>>(attp);
    softmax_kernel<<<2048, 256>>>(attp + ATT_N);

    dim3 gav(4, 32);
    av_kernel<<<gav, 256>>>(attp,         qkv + 2 * QKV_N, yb);           // y_g = att_g @ v_l
    av_kernel<<<gav, 256>>>(attp + ATT_N, qkv + 5 * QKV_N, yb + QKV_N);   // y_l = att_l @ v_g

    dim3 gproj(8, 4, 4);
    proj_kernel<<<gproj, 256>>>(yb + QKV_N, wpt,             x_l, rw, out_l); // Wp1
    proj_kernel<<<gproj, 256>>>(yb,         wpt + 512 * 512, x_g, rw, out_g); // Wp2
}

// round 5
// speedup vs baseline: 1.9623x; 1.9623x over previous
#include <cuda_runtime.h>
#include <cuda_bf16.h>
#include <cstdint>

// ---------------------------------------------------------------------------
// CrossAttention on GB300 (sm_103a, but PTX target lacks the 'a' feature:
// tcgen05 unavailable -> use sm_80-era mma.sync bf16 on the tensor pipe).
//  - six 3x3 convs -> implicit GEMM, mma.sync m16n8k16 bf16, 3-term hi/lo split
//  - attention (QK^T, softmax, AV) + 1x1 proj -> FFMA2 (fma.rn.f32x2) SIMT
// ---------------------------------------------------------------------------

#define NB   4
#define CCH  512
#define HW   1024
#define NHD  8
#define DHEAD 128

// Scratch (no allocations allowed -> __device__ globals)
__device__ float g_wA[6][9 * 512 * 512];         // [r][co][ci]
__device__ float g_wpt[2][512 * 512];            // [ci][co]
__device__ float g_xt[2][NB * HW * CCH];         // [n][hw][ci]
__device__ float g_qkv[6][NB * CCH * HW];        // kl,ql,vl,kg,qg,vg
__device__ float g_att[2][NB * NHD * 512 * 512]; // att_g, att_l
__device__ float g_y[2][NB * CCH * HW];          // y_g, y_l

// ============================ helpers =======================================
__device__ __forceinline__ uint32_t smem_u32(const void* p) {
    uint32_t a;
    asm("{ .reg .u64 t; cvta.to.shared.u64 t, %1; cvt.u32.u64 %0, t; }"
        : "=r"(a) : "l"(p));
    return a;
}

__device__ __forceinline__ void mma_bf16(float* c, const uint32_t* a, const uint32_t* b) {
    asm volatile(
        "mma.sync.aligned.m16n8k16.row.col.f32.bf16.bf16.f32 "
        "{%0,%1,%2,%3}, {%4,%5,%6,%7}, {%8,%9}, {%0,%1,%2,%3};"
        : "+f"(c[0]), "+f"(c[1]), "+f"(c[2]), "+f"(c[3])
        : "r"(a[0]), "r"(a[1]), "r"(a[2]), "r"(a[3]), "r"(b[0]), "r"(b[1]));
}

#define LDSM4(r0, r1, r2, r3, addr) \
    asm volatile("ldmatrix.sync.aligned.m8n8.x4.shared.b16 {%0,%1,%2,%3}, [%4];" \
                 : "=r"(r0), "=r"(r1), "=r"(r2), "=r"(r3) : "r"(addr))

#define STS64(addr, v0, v1) \
    asm volatile("st.shared.v2.u32 [%0], {%1,%2};" :: "r"(addr), "r"(v0), "r"(v1) : "memory")

// fp32x4 -> bf16 hi/lo packed pairs (k ascending in memory: low half = even k)
__device__ __forceinline__ void hilo4(float4 v, uint32_t h[2], uint32_t l[2]) {
    __nv_bfloat162 h01 = __floats2bfloat162_rn(v.x, v.y);
    __nv_bfloat162 h23 = __floats2bfloat162_rn(v.z, v.w);
    float2 f01 = __bfloat1622float2(h01);
    float2 f23 = __bfloat1622float2(h23);
    __nv_bfloat162 l01 = __floats2bfloat162_rn(v.x - f01.x, v.y - f01.y);
    __nv_bfloat162 l23 = __floats2bfloat162_rn(v.z - f23.x, v.w - f23.y);
    h[0] = *(uint32_t*)&h01; h[1] = *(uint32_t*)&h23;
    l[0] = *(uint32_t*)&l01; l[1] = *(uint32_t*)&l23;
}

// ============================ prep kernels ==================================
// w [co][ci][3][3] -> wA [r][co][ci]
__global__ void transpose_w3(const float* __restrict__ w, float* __restrict__ wt) {
    int t = blockIdx.x * 256 + threadIdx.x;          // 262144 (co,ci) pairs
    int co = t >> 9, ci = t & 511;
    float v[9];
#pragma unroll
    for (int r = 0; r < 9; ++r) v[r] = w[(size_t)t * 9 + r];
#pragma unroll
    for (int r = 0; r < 9; ++r) wt[((size_t)r * 512 + co) * 512 + ci] = v[r];
}
__global__ void transpose_w1(const float* __restrict__ w, float* __restrict__ wt) {
    int idx = blockIdx.x * 256 + threadIdx.x;
    int ci = idx & 511, co = idx >> 9;
    wt[ci * 512 + co] = w[idx];
}
// x [n][c][hw] -> xt [n][hw][c]
__global__ void transpose_x(const float* __restrict__ xl, const float* __restrict__ xg,
                            float* __restrict__ xtl, float* __restrict__ xtg) {
    __shared__ float tile[32][33];
    int zt = blockIdx.z, tsel = zt >> 2, n = zt & 3;
    const float* x = (tsel ? xg : xl) + (size_t)n * (CCH * HW);
    float* xt = (tsel ? xtg : xtl) + (size_t)n * (HW * CCH);
    int hw0 = blockIdx.x * 32, c0 = blockIdx.y * 32;
    int tx = threadIdx.x, ty = threadIdx.y;
#pragma unroll
    for (int i = 0; i < 32; i += 8)
        tile[ty + i][tx] = x[(size_t)(c0 + ty + i) * HW + hw0 + tx];
    __syncthreads();
#pragma unroll
    for (int i = 0; i < 32; i += 8)
        xt[(size_t)(hw0 + ty + i) * CCH + c0 + tx] = tile[tx][ty + i];
}

// ================== conv 3x3: mma.sync bf16 3x implicit GEMM ================
// grid (8 s-tiles, 4 co-tiles, 6 convs * 4 n), 256 threads = 8 warps (2x4).
// Block tile 128co x 128s, K = 9 taps * 512 ci in chunks of 32.
// Smem matrices: 128 rows x 32 bf16, row stride 80B (ldmatrix conflict-free).
#define ROWB 80
#define MATB (128 * ROWB)   // 10240 B

__global__ __launch_bounds__(256)
void conv_mma_kernel(const float* __restrict__ xt_l, const float* __restrict__ xt_g,
                     const float* __restrict__ wA, float* __restrict__ qkv) {
    __shared__ __align__(16) unsigned char sm[4 * MATB];
    const uint32_t sb  = smem_u32(sm);
    const uint32_t sAh = sb, sAl = sb + MATB, sBh = sb + 2 * MATB, sBl = sb + 3 * MATB;

    int tid = threadIdx.x, wid = tid >> 5, lid = tid & 31;
    int warp_m = wid >> 2, warp_n = wid & 3;
    int s0 = blockIdx.x * 128, co0 = blockIdx.y * 128;
    int conv = blockIdx.z >> 2, n = blockIdx.z & 3;
    const float* xt = (conv < 3 ? xt_l : xt_g) + (size_t)n * (HW * CCH);
    const float* wb = wA + (size_t)conv * (9 * 512 * 512);
    float* outb = qkv + ((size_t)conv * NB + n) * (CCH * HW);

    float acc[4][4][4];
#pragma unroll
    for (int mt = 0; mt < 4; ++mt)
#pragma unroll
        for (int nt = 0; nt < 4; ++nt)
#pragma unroll
            for (int k = 0; k < 4; ++k) acc[mt][nt][k] = 0.f;

    // per-lane ldmatrix base offsets
    int grp = lid >> 3, lr = lid & 7;
    uint32_t a_base = (uint32_t)((warp_m * 64 + (grp & 1) * 8 + lr) * ROWB + (grp >> 1) * 16);
    uint32_t b_base = (uint32_t)((warp_n * 32 + (grp & 1) * 8 + lr) * ROWB + (grp >> 1) * 16);

    // staging: each thread owns one matrix row-half (row = tid>>1, k-half = tid&1)
    int row = tid >> 1, kh = tid & 1;
    uint32_t so = (uint32_t)(row * ROWB + kh * 32);
    float4 ra[4], rb[4];

    auto stage = [&](int ch) {
        int r = ch >> 4, ci0 = (ch & 15) << 5;
        int dy = r / 3 - 1, dx = r % 3 - 1;
        const float* wr = wb + (size_t)r * (512 * 512) + (size_t)(co0 + row) * 512 + ci0 + kh * 16;
#pragma unroll
        for (int j = 0; j < 4; ++j) ra[j] = *(const float4*)(wr + 4 * j);
        int s = s0 + row;
        int yy = (s >> 5) + dy, xx = (s & 31) + dx;
        if ((unsigned)yy < 32u && (unsigned)xx < 32u) {
            const float* xr = xt + (size_t)(yy * 32 + xx) * 512 + ci0 + kh * 16;
#pragma unroll
            for (int j = 0; j < 4; ++j) rb[j] = *(const float4*)(xr + 4 * j);
        } else {
#pragma unroll
            for (int j = 0; j < 4; ++j) rb[j] = make_float4(0.f, 0.f, 0.f, 0.f);
        }
    };

    stage(0);
    for (int ch = 0; ch < 144; ++ch) {
        // fill smem (convert fp32 -> bf16 hi/lo)
#pragma unroll
        for (int j = 0; j < 4; ++j) {
            uint32_t h[2], l[2];
            hilo4(ra[j], h, l);
            STS64(sAh + so + j * 8, h[0], h[1]);
            STS64(sAl + so + j * 8, l[0], l[1]);
        }
#pragma unroll
        for (int j = 0; j < 4; ++j) {
            uint32_t h[2], l[2];
            hilo4(rb[j], h, l);
            STS64(sBh + so + j * 8, h[0], h[1]);
            STS64(sBl + so + j * 8, l[0], l[1]);
        }
        __syncthreads();
        if (ch + 1 < 144) stage(ch + 1);   // gmem prefetch overlaps MMA phase

#pragma unroll
        for (int kt = 0; kt < 2; ++kt) {
            uint32_t aH[4][4], aL[4][4], bH[4][2], bL[4][2];
#pragma unroll
            for (int mt = 0; mt < 4; ++mt) {
                uint32_t ad = a_base + (uint32_t)(mt * 16 * ROWB + kt * 32);
                LDSM4(aH[mt][0], aH[mt][1], aH[mt][2], aH[mt][3], sAh + ad);
                LDSM4(aL[mt][0], aL[mt][1], aL[mt][2], aL[mt][3], sAl + ad);
            }
#pragma unroll
            for (int p = 0; p < 2; ++p) {
                uint32_t bd = b_base + (uint32_t)(p * 16 * ROWB + kt * 32);
                uint32_t r0, r1, r2, r3;
                LDSM4(r0, r1, r2, r3, sBh + bd);
                bH[2 * p][0] = r0; bH[2 * p][1] = r2;
                bH[2 * p + 1][0] = r1; bH[2 * p + 1][1] = r3;
                LDSM4(r0, r1, r2, r3, sBl + bd);
                bL[2 * p][0] = r0; bL[2 * p][1] = r2;
                bL[2 * p + 1][0] = r1; bL[2 * p + 1][1] = r3;
            }
#pragma unroll
            for (int mt = 0; mt < 4; ++mt)
#pragma unroll
                for (int nt = 0; nt < 4; ++nt) {
                    mma_bf16(acc[mt][nt], aH[mt], bH[nt]);
                    mma_bf16(acc[mt][nt], aH[mt], bL[nt]);
                    mma_bf16(acc[mt][nt], aL[mt], bH[nt]);
                }
        }
        __syncthreads();
    }

    // epilogue: fragment (l>>2 = row, (l&3)*2 = col pair)
#pragma unroll
    for (int mt = 0; mt < 4; ++mt) {
        int m = co0 + warp_m * 64 + mt * 16 + (lid >> 2);
#pragma unroll
        for (int nt = 0; nt < 4; ++nt) {
            int sc = s0 + warp_n * 32 + nt * 8 + (lid & 3) * 2;
            *(float2*)(outb + (size_t)m * HW + sc) =
                make_float2(acc[mt][nt][0], acc[mt][nt][1]);
            *(float2*)(outb + (size_t)(m + 8) * HW + sc) =
                make_float2(acc[mt][nt][2], acc[mt][nt][3]);
        }
    }
}

// ======================= FFMA2 SIMT GEMM (attention) ========================
__device__ __forceinline__ unsigned long long pack2(float x, float y) {
    unsigned long long r;
    asm("mov.b64 %0, {%1, %2};" : "=l"(r) : "f"(x), "f"(y));
    return r;
}
__device__ __forceinline__ unsigned long long ffma2(unsigned long long a,
                                                    unsigned long long b,
                                                    unsigned long long c) {
    unsigned long long d;
    asm("fma.rn.f32x2 %0, %1, %2, %3;" : "=l"(d) : "l"(a), "l"(b), "l"(c));
    return d;
}
__device__ __forceinline__ void unpack2(unsigned long long v, float& x, float& y) {
    asm("mov.b64 {%0, %1}, %2;" : "=f"(x), "=f"(y) : "l"(v));
}

#define SMPAD 132
__device__ __forceinline__ void mma_chunk(const float (*As)[SMPAD],
                                          const float (*Bs)[SMPAD],
                                          int ty, int tx,
                                          unsigned long long acc[8][4]) {
#pragma unroll
    for (int k = 0; k < 16; ++k) {
        float4 a0 = *(const float4*)&As[k][ty * 8];
        float4 a1 = *(const float4*)&As[k][ty * 8 + 4];
        float4 b0 = *(const float4*)&Bs[k][tx * 8];
        float4 b1 = *(const float4*)&Bs[k][tx * 8 + 4];
        unsigned long long bp[4];
        bp[0] = pack2(b0.x, b0.y);
        bp[1] = pack2(b0.z, b0.w);
        bp[2] = pack2(b1.x, b1.y);
        bp[3] = pack2(b1.z, b1.w);
        float av[8] = {a0.x, a0.y, a0.z, a0.w, a1.x, a1.y, a1.z, a1.w};
#pragma unroll
        for (int i = 0; i < 8; ++i) {
            unsigned long long ad = pack2(av[i], av[i]);
#pragma unroll
            for (int j = 0; j < 4; ++j) acc[i][j] = ffma2(ad, bp[j], acc[i][j]);
        }
    }
}

__global__ __launch_bounds__(256, 2)
void qk_kernel(const float* __restrict__ q, const float* __restrict__ k,
               float* __restrict__ att) {
    __shared__ float As[16][SMPAD];
    __shared__ float Bs[16][SMPAD];
    int nh = blockIdx.z, n = nh >> 3, h = nh & 7;
    int ck0 = blockIdx.x * 128, cq0 = blockIdx.y * 128;
    int tid = threadIdx.x, tx = tid & 15, ty = tid >> 4;
    const float* qb = q + (size_t)n * (CCH * HW) + h * DHEAD;
    const float* kb = k + (size_t)n * (CCH * HW) + h * DHEAD;
    unsigned long long acc[8][4];
#pragma unroll
    for (int i = 0; i < 8; ++i)
#pragma unroll
        for (int j = 0; j < 4; ++j) acc[i][j] = 0ULL;

    for (int d0 = 0; d0 < DHEAD; d0 += 16) {
#pragma unroll
        for (int i = 0; i < 8; ++i) {
            int e = tid + i * 256;
            int cc = e >> 4, kk = e & 15;
            As[kk][cc] = qb[(size_t)(cq0 + cc) * HW + d0 + kk];
            Bs[kk][cc] = kb[(size_t)(ck0 + cc) * HW + d0 + kk];
        }
        __syncthreads();
        mma_chunk(As, Bs, ty, tx, acc);
        __syncthreads();
    }
    const float SC = 0.08838834764831845f;
#pragma unroll
    for (int i = 0; i < 8; ++i) {
        float o[8];
        unpack2(acc[i][0], o[0], o[1]);
        unpack2(acc[i][1], o[2], o[3]);
        unpack2(acc[i][2], o[4], o[5]);
        unpack2(acc[i][3], o[6], o[7]);
        float* dst = att + ((size_t)(n * NHD + h) * 512 + cq0 + ty * 8 + i) * 512
                         + ck0 + tx * 8;
        *(float4*)(dst)     = make_float4(o[0]*SC, o[1]*SC, o[2]*SC, o[3]*SC);
        *(float4*)(dst + 4) = make_float4(o[4]*SC, o[5]*SC, o[6]*SC, o[7]*SC);
    }
}

__global__ void softmax_kernel(float* __restrict__ att) {
    int row  = blockIdx.x * 8 + (threadIdx.x >> 5);
    int lane = threadIdx.x & 31;
    float* p = att + (size_t)row * 512;
    float v[16];
    float m = -1e30f;
#pragma unroll
    for (int i = 0; i < 16; ++i) { v[i] = p[lane + i * 32]; m = fmaxf(m, v[i]); }
#pragma unroll
    for (int o = 16; o; o >>= 1) m = fmaxf(m, __shfl_xor_sync(0xffffffffu, m, o));
    float s = 0.f;
#pragma unroll
    for (int i = 0; i < 16; ++i) { v[i] = __expf(v[i] - m); s += v[i]; }
#pragma unroll
    for (int o = 16; o; o >>= 1) s += __shfl_xor_sync(0xffffffffu, s, o);
    float inv = 1.f / s;
#pragma unroll
    for (int i = 0; i < 16; ++i) p[lane + i * 32] = v[i] * inv;
}

__global__ __launch_bounds__(256, 2)
void av_kernel(const float* __restrict__ att, const float* __restrict__ v,
               float* __restrict__ y) {
    __shared__ float As[16][SMPAD];
    __shared__ float Bs[16][SMPAD];
    int nh = blockIdx.y, n = nh >> 3, h = nh & 7;
    int cq0 = blockIdx.x * 128;
    int tid = threadIdx.x, tx = tid & 15, ty = tid >> 4;
    const float* ab = att + (size_t)(n * NHD + h) * 512 * 512;
    const float* vb = v + (size_t)n * (CCH * HW) + h * DHEAD;
    unsigned long long acc[8][4];
#pragma unroll
    for (int i = 0; i < 8; ++i)
#pragma unroll
        for (int j = 0; j < 4; ++j) acc[i][j] = 0ULL;

    for (int ck = 0; ck < 512; ck += 16) {
#pragma unroll
        for (int i = 0; i < 8; ++i) {
            int e = tid + i * 256;
            int cc = e >> 4, kk = e & 15;
            As[kk][cc] = ab[(size_t)(cq0 + cc) * 512 + ck + kk];
            int k2 = e >> 7, dd = e & 127;
            Bs[k2][dd] = vb[(size_t)(ck + k2) * HW + dd];
        }
        __syncthreads();
        mma_chunk(As, Bs, ty, tx, acc);
        __syncthreads();
    }
#pragma unroll
    for (int i = 0; i < 8; ++i) {
        float o[8];
        unpack2(acc[i][0], o[0], o[1]);
        unpack2(acc[i][1], o[2], o[3]);
        unpack2(acc[i][2], o[4], o[5]);
        unpack2(acc[i][3], o[6], o[7]);
        float* dst = y + ((size_t)n * CCH + cq0 + ty * 8 + i) * HW + h * DHEAD + tx * 8;
        *(float4*)(dst)     = make_float4(o[0], o[1], o[2], o[3]);
        *(float4*)(dst + 4) = make_float4(o[4], o[5], o[6], o[7]);
    }
}

__global__ __launch_bounds__(256, 2)
void proj_kernel(const float* __restrict__ y, const float* __restrict__ wpt,
                 const float* __restrict__ xres, const float* __restrict__ rwp,
                 float* __restrict__ out) {
    __shared__ float As[16][SMPAD];
    __shared__ float Bs[16][SMPAD];
    int s0 = blockIdx.x * 128, c0 = blockIdx.y * 128, n = blockIdx.z;
    int tid = threadIdx.x, tx = tid & 15, ty = tid >> 4;
    const float* yb = y + (size_t)n * (CCH * HW);
    unsigned long long acc[8][4];
#pragma unroll
    for (int i = 0; i < 8; ++i)
#pragma unroll
        for (int j = 0; j < 4; ++j) acc[i][j] = 0ULL;

    for (int c = 0; c < 512; c += 16) {
#pragma unroll
        for (int i = 0; i < 8; ++i) {
            int e = tid + i * 256;
            int kk = e >> 7, cc = e & 127;
            As[kk][cc] = wpt[(size_t)(c + kk) * 512 + c0 + cc];
            Bs[kk][cc] = yb[(size_t)(c + kk) * HW + s0 + cc];
        }
        __syncthreads();
        mma_chunk(As, Bs, ty, tx, acc);
        __syncthreads();
    }
    float rw = *rwp;
#pragma unroll
    for (int i = 0; i < 8; ++i) {
        float o[8];
        unpack2(acc[i][0], o[0], o[1]);
        unpack2(acc[i][1], o[2], o[3]);
        unpack2(acc[i][2], o[4], o[5]);
        unpack2(acc[i][3], o[6], o[7]);
        size_t basei = ((size_t)n * CCH + c0 + ty * 8 + i) * HW + s0 + tx * 8;
        float4 x0 = *(const float4*)(xres + basei);
        float4 x1 = *(const float4*)(xres + basei + 4);
        *(float4*)(out + basei) =
            make_float4(x0.x + rw * o[0], x0.y + rw * o[1],
                        x0.z + rw * o[2], x0.w + rw * o[3]);
        *(float4*)(out + basei + 4) =
            make_float4(x1.x + rw * o[4], x1.y + rw * o[5],
                        x1.z + rw * o[6], x1.w + rw * o[7]);
    }
}

// ------------------------------- launcher -----------------------------------
extern "C" void kernel_launch(void* const* d_in, const int* in_sizes, int n_in,
                              void* d_out, int out_size) {
    (void)in_sizes; (void)n_in; (void)out_size;
    const float* x_l = (const float*)d_in[0];
    const float* x_g = (const float*)d_in[1];
    const float* W3[6] = {(const float*)d_in[2], (const float*)d_in[3],
                          (const float*)d_in[4], (const float*)d_in[5],
                          (const float*)d_in[6], (const float*)d_in[7]};
    const float* Wp1 = (const float*)d_in[8];
    const float* Wp2 = (const float*)d_in[9];
    const float* rw  = (const float*)d_in[10];
    float* out_l = (float*)d_out;
    float* out_g = out_l + (size_t)NB * CCH * HW;

    void* p;
    cudaGetSymbolAddress(&p, g_wA);   float* wA   = (float*)p;
    cudaGetSymbolAddress(&p, g_wpt);  float* wpt  = (float*)p;
    cudaGetSymbolAddress(&p, g_xt);   float* xt   = (float*)p;
    cudaGetSymbolAddress(&p, g_qkv);  float* qkv  = (float*)p;
    cudaGetSymbolAddress(&p, g_att);  float* attp = (float*)p;
    cudaGetSymbolAddress(&p, g_y);    float* yb   = (float*)p;

    const size_t WT_N  = (size_t)9 * 512 * 512;
    const size_t XT_N  = (size_t)NB * HW * CCH;
    const size_t QKV_N = (size_t)NB * CCH * HW;
    const size_t ATT_N = (size_t)NB * NHD * 512 * 512;

    for (int i = 0; i < 6; ++i)
        transpose_w3<<<1024, 256>>>(W3[i], wA + i * WT_N);
    transpose_w1<<<1024, 256>>>(Wp1, wpt);
    transpose_w1<<<1024, 256>>>(Wp2, wpt + 512 * 512);
    transpose_x<<<dim3(32, 16, 8), dim3(32, 8)>>>(x_l, x_g, xt, xt + XT_N);

    // all six convs in one launch: z = conv*4 + n
    conv_mma_kernel<<<dim3(8, 4, 24), 256>>>(xt, xt + XT_N, wA, qkv);

    dim3 gqk(4, 4, 32);
    qk_kernel<<<gqk, 256>>>(qkv + 4 * QKV_N, qkv + 0 * QKV_N, attp);          // q_g, k_l
    qk_kernel<<<gqk, 256>>>(qkv + 1 * QKV_N, qkv + 3 * QKV_N, attp + ATT_N);  // q_l, k_g

    softmax_kernel<<<2048, 256>>>(attp);
    softmax_kernel<<<2048, 256>>>(attp + ATT_N);

    dim3 gav(4, 32);
    av_kernel<<<gav, 256>>>(attp,         qkv + 2 * QKV_N, yb);           // y_g
    av_kernel<<<gav, 256>>>(attp + ATT_N, qkv + 5 * QKV_N, yb + QKV_N);   // y_l

    dim3 gproj(8, 4, 4);
    proj_kernel<<<gproj, 256>>>(yb + QKV_N, wpt,             x_l, rw, out_l);
    proj_kernel<<<gproj, 256>>>(yb,         wpt + 512 * 512, x_g, rw, out_g);
}

// round 6
// speedup vs baseline: 2.2302x; 1.1365x over previous
#include <cuda_runtime.h>
#include <cuda_bf16.h>
#include <cstdint>

// ---------------------------------------------------------------------------
// CrossAttention on GB300 (sm_103a; PTX target is plain compute_103 ->
// tcgen05 unavailable; tensor pipe driven via sm_80-era mma.sync bf16).
// ALL GEMMs (6x conv3x3, QK^T, AV, 1x1 proj) use mma.sync m16n8k16 bf16 with
// a 3-term hi/lo split (AhBh + AhBl + AlBh, fp32 accum).
// ---------------------------------------------------------------------------

#define NB   4
#define CCH  512
#define HW   1024
#define NHD  8
#define DHEAD 128

// Scratch (no allocations allowed -> __device__ globals)
__device__ float g_wA[6][9 * 512 * 512];         // [r][co][ci]
__device__ float g_xt[2][NB * HW * CCH];         // [n][hw][ci]
__device__ float g_qkv[6][NB * CCH * HW];        // kl,ql,vl,kg,qg,vg
__device__ float g_att[2][NB * NHD * 512 * 512]; // att_g, att_l
__device__ float g_y[2][NB * CCH * HW];          // y_g, y_l

// ============================ helpers =======================================
__device__ __forceinline__ uint32_t smem_u32(const void* p) {
    uint32_t a;
    asm("{ .reg .u64 t; cvta.to.shared.u64 t, %1; cvt.u32.u64 %0, t; }"
        : "=r"(a) : "l"(p));
    return a;
}

__device__ __forceinline__ void mma_bf16(float* c, const uint32_t* a, const uint32_t* b) {
    asm volatile(
        "mma.sync.aligned.m16n8k16.row.col.f32.bf16.bf16.f32 "
        "{%0,%1,%2,%3}, {%4,%5,%6,%7}, {%8,%9}, {%0,%1,%2,%3};"
        : "+f"(c[0]), "+f"(c[1]), "+f"(c[2]), "+f"(c[3])
        : "r"(a[0]), "r"(a[1]), "r"(a[2]), "r"(a[3]), "r"(b[0]), "r"(b[1]));
}

#define LDSM4(r0, r1, r2, r3, addr) \
    asm volatile("ldmatrix.sync.aligned.m8n8.x4.shared.b16 {%0,%1,%2,%3}, [%4];" \
                 : "=r"(r0), "=r"(r1), "=r"(r2), "=r"(r3) : "r"(addr))

#define LDSM2T(r0, r1, addr) \
    asm volatile("ldmatrix.sync.aligned.m8n8.x2.trans.shared.b16 {%0,%1}, [%2];" \
                 : "=r"(r0), "=r"(r1) : "r"(addr))

#define STS64(addr, v0, v1) \
    asm volatile("st.shared.v2.u32 [%0], {%1,%2};" :: "r"(addr), "r"(v0), "r"(v1) : "memory")

// fp32x4 -> bf16 hi/lo packed pairs
__device__ __forceinline__ void hilo4(float4 v, uint32_t h[2], uint32_t l[2]) {
    __nv_bfloat162 h01 = __floats2bfloat162_rn(v.x, v.y);
    __nv_bfloat162 h23 = __floats2bfloat162_rn(v.z, v.w);
    float2 f01 = __bfloat1622float2(h01);
    float2 f23 = __bfloat1622float2(h23);
    __nv_bfloat162 l01 = __floats2bfloat162_rn(v.x - f01.x, v.y - f01.y);
    __nv_bfloat162 l23 = __floats2bfloat162_rn(v.z - f23.x, v.w - f23.y);
    h[0] = *(uint32_t*)&h01; h[1] = *(uint32_t*)&h23;
    l[0] = *(uint32_t*)&l01; l[1] = *(uint32_t*)&l23;
}

// ============================ prep kernels ==================================
// w [co][ci][3][3] -> wA [r][co][ci]; one launch for all six convs
__global__ void transpose_w3_all(const float* __restrict__ w0, const float* __restrict__ w1,
                                 const float* __restrict__ w2, const float* __restrict__ w3,
                                 const float* __restrict__ w4, const float* __restrict__ w5,
                                 float* __restrict__ wt) {
    const float* ws[6] = {w0, w1, w2, w3, w4, w5};
    int conv = blockIdx.y;
    const float* w = ws[conv];
    float* wtc = wt + (size_t)conv * (9 * 512 * 512);
    int t = blockIdx.x * 256 + threadIdx.x;
    int co = t >> 9, ci = t & 511;
    float v[9];
#pragma unroll
    for (int r = 0; r < 9; ++r) v[r] = w[(size_t)t * 9 + r];
#pragma unroll
    for (int r = 0; r < 9; ++r) wtc[((size_t)r * 512 + co) * 512 + ci] = v[r];
}
// x [n][c][hw] -> xt [n][hw][c]
__global__ void transpose_x(const float* __restrict__ xl, const float* __restrict__ xg,
                            float* __restrict__ xtl, float* __restrict__ xtg) {
    __shared__ float tile[32][33];
    int zt = blockIdx.z, tsel = zt >> 2, n = zt & 3;
    const float* x = (tsel ? xg : xl) + (size_t)n * (CCH * HW);
    float* xt = (tsel ? xtg : xtl) + (size_t)n * (HW * CCH);
    int hw0 = blockIdx.x * 32, c0 = blockIdx.y * 32;
    int tx = threadIdx.x, ty = threadIdx.y;
#pragma unroll
    for (int i = 0; i < 32; i += 8)
        tile[ty + i][tx] = x[(size_t)(c0 + ty + i) * HW + hw0 + tx];
    __syncthreads();
#pragma unroll
    for (int i = 0; i < 32; i += 8)
        xt[(size_t)(hw0 + ty + i) * CCH + c0 + tx] = tile[tx][ty + i];
}

// ================== conv 3x3: mma.sync bf16 3x implicit GEMM ================
#define ROWB 80
#define MATB (128 * ROWB)   // 10240 B
#define ROW2 272            // B-trans layout: 128 bf16 + 16B pad
#define MATB2 (32 * ROW2)   // 8704 B

__global__ __launch_bounds__(256)
void conv_mma_kernel(const float* __restrict__ xt_l, const float* __restrict__ xt_g,
                     const float* __restrict__ wA, float* __restrict__ qkv) {
    __shared__ __align__(16) unsigned char sm[4 * MATB];
    const uint32_t sb  = smem_u32(sm);
    const uint32_t sAh = sb, sAl = sb + MATB, sBh = sb + 2 * MATB, sBl = sb + 3 * MATB;

    int tid = threadIdx.x, wid = tid >> 5, lid = tid & 31;
    int warp_m = wid >> 2, warp_n = wid & 3;
    int s0 = blockIdx.x * 128, co0 = blockIdx.y * 128;
    int conv = blockIdx.z >> 2, n = blockIdx.z & 3;
    const float* xt = (conv < 3 ? xt_l : xt_g) + (size_t)n * (HW * CCH);
    const float* wb = wA + (size_t)conv * (9 * 512 * 512);
    float* outb = qkv + ((size_t)conv * NB + n) * (CCH * HW);

    float acc[4][4][4];
#pragma unroll
    for (int mt = 0; mt < 4; ++mt)
#pragma unroll
        for (int nt = 0; nt < 4; ++nt)
#pragma unroll
            for (int k = 0; k < 4; ++k) acc[mt][nt][k] = 0.f;

    int grp = lid >> 3, lr = lid & 7;
    uint32_t a_base = (uint32_t)((warp_m * 64 + (grp & 1) * 8 + lr) * ROWB + (grp >> 1) * 16);
    uint32_t b_base = (uint32_t)((warp_n * 32 + (grp & 1) * 8 + lr) * ROWB + (grp >> 1) * 16);

    int row = tid >> 1, kh = tid & 1;
    uint32_t so = (uint32_t)(row * ROWB + kh * 32);
    float4 ra[4], rb[4];

    auto stage = [&](int ch) {
        int r = ch >> 4, ci0 = (ch & 15) << 5;
        int dy = r / 3 - 1, dx = r % 3 - 1;
        const float* wr = wb + (size_t)r * (512 * 512) + (size_t)(co0 + row) * 512 + ci0 + kh * 16;
#pragma unroll
        for (int j = 0; j < 4; ++j) ra[j] = *(const float4*)(wr + 4 * j);
        int s = s0 + row;
        int yy = (s >> 5) + dy, xx = (s & 31) + dx;
        if ((unsigned)yy < 32u && (unsigned)xx < 32u) {
            const float* xr = xt + (size_t)(yy * 32 + xx) * 512 + ci0 + kh * 16;
#pragma unroll
            for (int j = 0; j < 4; ++j) rb[j] = *(const float4*)(xr + 4 * j);
        } else {
#pragma unroll
            for (int j = 0; j < 4; ++j) rb[j] = make_float4(0.f, 0.f, 0.f, 0.f);
        }
    };

    stage(0);
    for (int ch = 0; ch < 144; ++ch) {
#pragma unroll
        for (int j = 0; j < 4; ++j) {
            uint32_t h[2], l[2];
            hilo4(ra[j], h, l);
            STS64(sAh + so + j * 8, h[0], h[1]);
            STS64(sAl + so + j * 8, l[0], l[1]);
        }
#pragma unroll
        for (int j = 0; j < 4; ++j) {
            uint32_t h[2], l[2];
            hilo4(rb[j], h, l);
            STS64(sBh + so + j * 8, h[0], h[1]);
            STS64(sBl + so + j * 8, l[0], l[1]);
        }
        __syncthreads();
        if (ch + 1 < 144) stage(ch + 1);

#pragma unroll
        for (int kt = 0; kt < 2; ++kt) {
            uint32_t aH[4][4], aL[4][4], bH[4][2], bL[4][2];
#pragma unroll
            for (int mt = 0; mt < 4; ++mt) {
                uint32_t ad = a_base + (uint32_t)(mt * 16 * ROWB + kt * 32);
                LDSM4(aH[mt][0], aH[mt][1], aH[mt][2], aH[mt][3], sAh + ad);
                LDSM4(aL[mt][0], aL[mt][1], aL[mt][2], aL[mt][3], sAl + ad);
            }
#pragma unroll
            for (int p = 0; p < 2; ++p) {
                uint32_t bd = b_base + (uint32_t)(p * 16 * ROWB + kt * 32);
                uint32_t r0, r1, r2, r3;
                LDSM4(r0, r1, r2, r3, sBh + bd);
                bH[2 * p][0] = r0; bH[2 * p][1] = r2;
                bH[2 * p + 1][0] = r1; bH[2 * p + 1][1] = r3;
                LDSM4(r0, r1, r2, r3, sBl + bd);
                bL[2 * p][0] = r0; bL[2 * p][1] = r2;
                bL[2 * p + 1][0] = r1; bL[2 * p + 1][1] = r3;
            }
#pragma unroll
            for (int mt = 0; mt < 4; ++mt)
#pragma unroll
                for (int nt = 0; nt < 4; ++nt) {
                    mma_bf16(acc[mt][nt], aH[mt], bH[nt]);
                    mma_bf16(acc[mt][nt], aH[mt], bL[nt]);
                    mma_bf16(acc[mt][nt], aL[mt], bH[nt]);
                }
        }
        __syncthreads();
    }

#pragma unroll
    for (int mt = 0; mt < 4; ++mt) {
        int m = co0 + warp_m * 64 + mt * 16 + (lid >> 2);
#pragma unroll
        for (int nt = 0; nt < 4; ++nt) {
            int sc = s0 + warp_n * 32 + nt * 8 + (lid & 3) * 2;
            *(float2*)(outb + (size_t)m * HW + sc) =
                make_float2(acc[mt][nt][0], acc[mt][nt][1]);
            *(float2*)(outb + (size_t)(m + 8) * HW + sc) =
                make_float2(acc[mt][nt][2], acc[mt][nt][3]);
        }
    }
}

// ======================== QK^T: mma.sync bf16 3x ============================
// grid (4 ck-tiles, 4 cq-tiles, 32 nh). Both operands row-major d-contiguous.
__global__ __launch_bounds__(256)
void qk_mma_kernel(const float* __restrict__ q, const float* __restrict__ k,
                   float* __restrict__ att) {
    __shared__ __align__(16) unsigned char sm[4 * MATB];
    const uint32_t sb  = smem_u32(sm);
    const uint32_t sAh = sb, sAl = sb + MATB, sBh = sb + 2 * MATB, sBl = sb + 3 * MATB;

    int tid = threadIdx.x, wid = tid >> 5, lid = tid & 31;
    int warp_m = wid >> 2, warp_n = wid & 3;
    int nh = blockIdx.z, n = nh >> 3, h = nh & 7;
    int ck0 = blockIdx.x * 128, cq0 = blockIdx.y * 128;
    const float* qb = q + (size_t)n * (CCH * HW) + h * DHEAD;
    const float* kb = k + (size_t)n * (CCH * HW) + h * DHEAD;

    float acc[4][4][4];
#pragma unroll
    for (int mt = 0; mt < 4; ++mt)
#pragma unroll
        for (int nt = 0; nt < 4; ++nt)
#pragma unroll
            for (int kk = 0; kk < 4; ++kk) acc[mt][nt][kk] = 0.f;

    int grp = lid >> 3, lr = lid & 7;
    uint32_t a_base = (uint32_t)((warp_m * 64 + (grp & 1) * 8 + lr) * ROWB + (grp >> 1) * 16);
    uint32_t b_base = (uint32_t)((warp_n * 32 + (grp & 1) * 8 + lr) * ROWB + (grp >> 1) * 16);

    int row = tid >> 1, kh = tid & 1;
    uint32_t so = (uint32_t)(row * ROWB + kh * 32);
    float4 ra[4], rb[4];

    auto stage = [&](int ch) {
        int ci0 = ch << 5;
        const float* qr = qb + (size_t)(cq0 + row) * HW + ci0 + kh * 16;
        const float* kr = kb + (size_t)(ck0 + row) * HW + ci0 + kh * 16;
#pragma unroll
        for (int j = 0; j < 4; ++j) ra[j] = *(const float4*)(qr + 4 * j);
#pragma unroll
        for (int j = 0; j < 4; ++j) rb[j] = *(const float4*)(kr + 4 * j);
    };

    stage(0);
    for (int ch = 0; ch < 4; ++ch) {
#pragma unroll
        for (int j = 0; j < 4; ++j) {
            uint32_t h2[2], l2[2];
            hilo4(ra[j], h2, l2);
            STS64(sAh + so + j * 8, h2[0], h2[1]);
            STS64(sAl + so + j * 8, l2[0], l2[1]);
        }
#pragma unroll
        for (int j = 0; j < 4; ++j) {
            uint32_t h2[2], l2[2];
            hilo4(rb[j], h2, l2);
            STS64(sBh + so + j * 8, h2[0], h2[1]);
            STS64(sBl + so + j * 8, l2[0], l2[1]);
        }
        __syncthreads();
        if (ch + 1 < 4) stage(ch + 1);

#pragma unroll
        for (int kt = 0; kt < 2; ++kt) {
            uint32_t aH[4][4], aL[4][4], bH[4][2], bL[4][2];
#pragma unroll
            for (int mt = 0; mt < 4; ++mt) {
                uint32_t ad = a_base + (uint32_t)(mt * 16 * ROWB + kt * 32);
                LDSM4(aH[mt][0], aH[mt][1], aH[mt][2], aH[mt][3], sAh + ad);
                LDSM4(aL[mt][0], aL[mt][1], aL[mt][2], aL[mt][3], sAl + ad);
            }
#pragma unroll
            for (int p = 0; p < 2; ++p) {
                uint32_t bd = b_base + (uint32_t)(p * 16 * ROWB + kt * 32);
                uint32_t r0, r1, r2, r3;
                LDSM4(r0, r1, r2, r3, sBh + bd);
                bH[2 * p][0] = r0; bH[2 * p][1] = r2;
                bH[2 * p + 1][0] = r1; bH[2 * p + 1][1] = r3;
                LDSM4(r0, r1, r2, r3, sBl + bd);
                bL[2 * p][0] = r0; bL[2 * p][1] = r2;
                bL[2 * p + 1][0] = r1; bL[2 * p + 1][1] = r3;
            }
#pragma unroll
            for (int mt = 0; mt < 4; ++mt)
#pragma unroll
                for (int nt = 0; nt < 4; ++nt) {
                    mma_bf16(acc[mt][nt], aH[mt], bH[nt]);
                    mma_bf16(acc[mt][nt], aH[mt], bL[nt]);
                    mma_bf16(acc[mt][nt], aL[mt], bH[nt]);
                }
        }
        __syncthreads();
    }

    const float SC = 0.08838834764831845f;   // 1/sqrt(128)
    float* ab = att + (size_t)(n * NHD + h) * 512 * 512;
#pragma unroll
    for (int mt = 0; mt < 4; ++mt) {
        int m = cq0 + warp_m * 64 + mt * 16 + (lid >> 2);
#pragma unroll
        for (int nt = 0; nt < 4; ++nt) {
            int sc = ck0 + warp_n * 32 + nt * 8 + (lid & 3) * 2;
            *(float2*)(ab + (size_t)m * 512 + sc) =
                make_float2(acc[mt][nt][0] * SC, acc[mt][nt][1] * SC);
            *(float2*)(ab + (size_t)(m + 8) * 512 + sc) =
                make_float2(acc[mt][nt][2] * SC, acc[mt][nt][3] * SC);
        }
    }
}

// ------------------------------- softmax ------------------------------------
__global__ void softmax_kernel(float* __restrict__ att) {
    int row  = blockIdx.x * 8 + (threadIdx.x >> 5);
    int lane = threadIdx.x & 31;
    float* p = att + (size_t)row * 512;
    float v[16];
    float m = -1e30f;
#pragma unroll
    for (int i = 0; i < 16; ++i) { v[i] = p[lane + i * 32]; m = fmaxf(m, v[i]); }
#pragma unroll
    for (int o = 16; o; o >>= 1) m = fmaxf(m, __shfl_xor_sync(0xffffffffu, m, o));
    float s = 0.f;
#pragma unroll
    for (int i = 0; i < 16; ++i) { v[i] = __expf(v[i] - m); s += v[i]; }
#pragma unroll
    for (int o = 16; o; o >>= 1) s += __shfl_xor_sync(0xffffffffu, s, o);
    float inv = 1.f / s;
#pragma unroll
    for (int i = 0; i < 16; ++i) p[lane + i * 32] = v[i] * inv;
}

// ===================== AV: mma.sync bf16 3x, B via ldsm.trans ===============
// grid (4 cq-tiles, 32 nh). C[128 cq x 128 d]; K = 512 ck (16 chunks).
// A = att rows (k-contig, normal path). B = V stored [ck][d] -> ldmatrix.trans.
__global__ __launch_bounds__(256)
void av_mma_kernel(const float* __restrict__ att, const float* __restrict__ v,
                   float* __restrict__ y) {
    __shared__ __align__(16) unsigned char sm[2 * MATB + 2 * MATB2];
    const uint32_t sb  = smem_u32(sm);
    const uint32_t sAh = sb, sAl = sb + MATB;
    const uint32_t sBh = sb + 2 * MATB, sBl = sb + 2 * MATB + MATB2;

    int tid = threadIdx.x, wid = tid >> 5, lid = tid & 31;
    int warp_m = wid >> 2, warp_n = wid & 3;
    int nh = blockIdx.y, n = nh >> 3, h = nh & 7;
    int cq0 = blockIdx.x * 128;
    const float* ab = att + (size_t)(n * NHD + h) * 512 * 512;
    const float* vb = v + (size_t)n * (CCH * HW) + h * DHEAD;

    float acc[4][4][4];
#pragma unroll
    for (int mt = 0; mt < 4; ++mt)
#pragma unroll
        for (int nt = 0; nt < 4; ++nt)
#pragma unroll
            for (int kk = 0; kk < 4; ++kk) acc[mt][nt][kk] = 0.f;

    int grp = lid >> 3, lr = lid & 7;
    uint32_t a_base = (uint32_t)((warp_m * 64 + (grp & 1) * 8 + lr) * ROWB + (grp >> 1) * 16);
    int l16 = lid & 15;
    uint32_t bt_base = (uint32_t)(l16 * ROW2 + warp_n * 64);   // 32 d * 2B

    int row = tid >> 1, kh = tid & 1;
    uint32_t soA = (uint32_t)(row * ROWB + kh * 32);
    int ckr = tid >> 3, dseg = (tid & 7) * 16;
    uint32_t soB = (uint32_t)(ckr * ROW2 + dseg * 2);
    float4 ra[4], rb[4];

    auto stage = [&](int ch) {
        int ci0 = ch << 5;
        const float* ar = ab + (size_t)(cq0 + row) * 512 + ci0 + kh * 16;
#pragma unroll
        for (int j = 0; j < 4; ++j) ra[j] = *(const float4*)(ar + 4 * j);
        const float* vr = vb + (size_t)(ci0 + ckr) * HW + dseg;
#pragma unroll
        for (int j = 0; j < 4; ++j) rb[j] = *(const float4*)(vr + 4 * j);
    };

    stage(0);
    for (int ch = 0; ch < 16; ++ch) {
#pragma unroll
        for (int j = 0; j < 4; ++j) {
            uint32_t h2[2], l2[2];
            hilo4(ra[j], h2, l2);
            STS64(sAh + soA + j * 8, h2[0], h2[1]);
            STS64(sAl + soA + j * 8, l2[0], l2[1]);
        }
#pragma unroll
        for (int j = 0; j < 4; ++j) {
            uint32_t h2[2], l2[2];
            hilo4(rb[j], h2, l2);
            STS64(sBh + soB + j * 8, h2[0], h2[1]);
            STS64(sBl + soB + j * 8, l2[0], l2[1]);
        }
        __syncthreads();
        if (ch + 1 < 16) stage(ch + 1);

#pragma unroll
        for (int kt = 0; kt < 2; ++kt) {
            uint32_t aH[4][4], aL[4][4], bH[4][2], bL[4][2];
#pragma unroll
            for (int mt = 0; mt < 4; ++mt) {
                uint32_t ad = a_base + (uint32_t)(mt * 16 * ROWB + kt * 32);
                LDSM4(aH[mt][0], aH[mt][1], aH[mt][2], aH[mt][3], sAh + ad);
                LDSM4(aL[mt][0], aL[mt][1], aL[mt][2], aL[mt][3], sAl + ad);
            }
#pragma unroll
            for (int nt = 0; nt < 4; ++nt) {
                uint32_t bd = bt_base + (uint32_t)(kt * 16 * ROW2 + nt * 16);
                LDSM2T(bH[nt][0], bH[nt][1], sBh + bd);
                LDSM2T(bL[nt][0], bL[nt][1], sBl + bd);
            }
#pragma unroll
            for (int mt = 0; mt < 4; ++mt)
#pragma unroll
                for (int nt = 0; nt < 4; ++nt) {
                    mma_bf16(acc[mt][nt], aH[mt], bH[nt]);
                    mma_bf16(acc[mt][nt], aH[mt], bL[nt]);
                    mma_bf16(acc[mt][nt], aL[mt], bH[nt]);
                }
        }
        __syncthreads();
    }

    float* yb = y + (size_t)n * (CCH * HW) + h * DHEAD;
#pragma unroll
    for (int mt = 0; mt < 4; ++mt) {
        int m = cq0 + warp_m * 64 + mt * 16 + (lid >> 2);
#pragma unroll
        for (int nt = 0; nt < 4; ++nt) {
            int dc = warp_n * 32 + nt * 8 + (lid & 3) * 2;
            *(float2*)(yb + (size_t)m * HW + dc) =
                make_float2(acc[mt][nt][0], acc[mt][nt][1]);
            *(float2*)(yb + (size_t)(m + 8) * HW + dc) =
                make_float2(acc[mt][nt][2], acc[mt][nt][3]);
        }
    }
}

// ============ 1x1 proj + residual: mma.sync bf16 3x, B via trans ============
// grid (8 s-tiles, 4 co-tiles, 4 n). A = Wp [co][ci] (native layout!).
// B = Y stored [ci][s] -> ldmatrix.trans. K = 512 ci (16 chunks).
__global__ __launch_bounds__(256)
void proj_mma_kernel(const float* __restrict__ y, const float* __restrict__ wp,
                     const float* __restrict__ xres, const float* __restrict__ rwp,
                     float* __restrict__ out) {
    __shared__ __align__(16) unsigned char sm[2 * MATB + 2 * MATB2];
    const uint32_t sb  = smem_u32(sm);
    const uint32_t sAh = sb, sAl = sb + MATB;
    const uint32_t sBh = sb + 2 * MATB, sBl = sb + 2 * MATB + MATB2;

    int tid = threadIdx.x, wid = tid >> 5, lid = tid & 31;
    int warp_m = wid >> 2, warp_n = wid & 3;
    int s0 = blockIdx.x * 128, co0 = blockIdx.y * 128, n = blockIdx.z;
    const float* yb = y + (size_t)n * (CCH * HW);

    float acc[4][4][4];
#pragma unroll
    for (int mt = 0; mt < 4; ++mt)
#pragma unroll
        for (int nt = 0; nt < 4; ++nt)
#pragma unroll
            for (int kk = 0; kk < 4; ++kk) acc[mt][nt][kk] = 0.f;

    int grp = lid >> 3, lr = lid & 7;
    uint32_t a_base = (uint32_t)((warp_m * 64 + (grp & 1) * 8 + lr) * ROWB + (grp >> 1) * 16);
    int l16 = lid & 15;
    uint32_t bt_base = (uint32_t)(l16 * ROW2 + warp_n * 64);

    int row = tid >> 1, kh = tid & 1;
    uint32_t soA = (uint32_t)(row * ROWB + kh * 32);
    int cir = tid >> 3, sseg = (tid & 7) * 16;
    uint32_t soB = (uint32_t)(cir * ROW2 + sseg * 2);
    float4 ra[4], rb[4];

    auto stage = [&](int ch) {
        int ci0 = ch << 5;
        const float* wr = wp + (size_t)(co0 + row) * 512 + ci0 + kh * 16;
#pragma unroll
        for (int j = 0; j < 4; ++j) ra[j] = *(const float4*)(wr + 4 * j);
        const float* yr = yb + (size_t)(ci0 + cir) * HW + s0 + sseg;
#pragma unroll
        for (int j = 0; j < 4; ++j) rb[j] = *(const float4*)(yr + 4 * j);
    };

    stage(0);
    for (int ch = 0; ch < 16; ++ch) {
#pragma unroll
        for (int j = 0; j < 4; ++j) {
            uint32_t h2[2], l2[2];
            hilo4(ra[j], h2, l2);
            STS64(sAh + soA + j * 8, h2[0], h2[1]);
            STS64(sAl + soA + j * 8, l2[0], l2[1]);
        }
#pragma unroll
        for (int j = 0; j < 4; ++j) {
            uint32_t h2[2], l2[2];
            hilo4(rb[j], h2, l2);
            STS64(sBh + soB + j * 8, h2[0], h2[1]);
            STS64(sBl + soB + j * 8, l2[0], l2[1]);
        }
        __syncthreads();
        if (ch + 1 < 16) stage(ch + 1);

#pragma unroll
        for (int kt = 0; kt < 2; ++kt) {
            uint32_t aH[4][4], aL[4][4], bH[4][2], bL[4][2];
#pragma unroll
            for (int mt = 0; mt < 4; ++mt) {
                uint32_t ad = a_base + (uint32_t)(mt * 16 * ROWB + kt * 32);
                LDSM4(aH[mt][0], aH[mt][1], aH[mt][2], aH[mt][3], sAh + ad);
                LDSM4(aL[mt][0], aL[mt][1], aL[mt][2], aL[mt][3], sAl + ad);
            }
#pragma unroll
            for (int nt = 0; nt < 4; ++nt) {
                uint32_t bd = bt_base + (uint32_t)(kt * 16 * ROW2 + nt * 16);
                LDSM2T(bH[nt][0], bH[nt][1], sBh + bd);
                LDSM2T(bL[nt][0], bL[nt][1], sBl + bd);
            }
#pragma unroll
            for (int mt = 0; mt < 4; ++mt)
#pragma unroll
                for (int nt = 0; nt < 4; ++nt) {
                    mma_bf16(acc[mt][nt], aH[mt], bH[nt]);
                    mma_bf16(acc[mt][nt], aH[mt], bL[nt]);
                    mma_bf16(acc[mt][nt], aL[mt], bH[nt]);
                }
        }
        __syncthreads();
    }

    float rw = *rwp;
#pragma unroll
    for (int mt = 0; mt < 4; ++mt) {
        int m = co0 + warp_m * 64 + mt * 16 + (lid >> 2);
#pragma unroll
        for (int nt = 0; nt < 4; ++nt) {
            int sc = s0 + warp_n * 32 + nt * 8 + (lid & 3) * 2;
            size_t b0 = ((size_t)n * CCH + m) * HW + sc;
            size_t b1 = ((size_t)n * CCH + m + 8) * HW + sc;
            float2 x0 = *(const float2*)(xres + b0);
            float2 x1 = *(const float2*)(xres + b1);
            *(float2*)(out + b0) = make_float2(x0.x + rw * acc[mt][nt][0],
                                               x0.y + rw * acc[mt][nt][1]);
            *(float2*)(out + b1) = make_float2(x1.x + rw * acc[mt][nt][2],
                                               x1.y + rw * acc[mt][nt][3]);
        }
    }
}

// ------------------------------- launcher -----------------------------------
extern "C" void kernel_launch(void* const* d_in, const int* in_sizes, int n_in,
                              void* d_out, int out_size) {
    (void)in_sizes; (void)n_in; (void)out_size;
    const float* x_l = (const float*)d_in[0];
    const float* x_g = (const float*)d_in[1];
    const float* Wp1 = (const float*)d_in[8];
    const float* Wp2 = (const float*)d_in[9];
    const float* rw  = (const float*)d_in[10];
    float* out_l = (float*)d_out;
    float* out_g = out_l + (size_t)NB * CCH * HW;

    void* p;
    cudaGetSymbolAddress(&p, g_wA);   float* wA   = (float*)p;
    cudaGetSymbolAddress(&p, g_xt);   float* xt   = (float*)p;
    cudaGetSymbolAddress(&p, g_qkv);  float* qkv  = (float*)p;
    cudaGetSymbolAddress(&p, g_att);  float* attp = (float*)p;
    cudaGetSymbolAddress(&p, g_y);    float* yb   = (float*)p;

    const size_t XT_N  = (size_t)NB * HW * CCH;
    const size_t QKV_N = (size_t)NB * CCH * HW;
    const size_t ATT_N = (size_t)NB * NHD * 512 * 512;

    transpose_w3_all<<<dim3(1024, 6), 256>>>(
        (const float*)d_in[2], (const float*)d_in[3], (const float*)d_in[4],
        (const float*)d_in[5], (const float*)d_in[6], (const float*)d_in[7], wA);
    transpose_x<<<dim3(32, 16, 8), dim3(32, 8)>>>(x_l, x_g, xt, xt + XT_N);

    conv_mma_kernel<<<dim3(8, 4, 24), 256>>>(xt, xt + XT_N, wA, qkv);

    dim3 gqk(4, 4, 32);
    qk_mma_kernel<<<gqk, 256>>>(qkv + 4 * QKV_N, qkv + 0 * QKV_N, attp);          // q_g, k_l
    qk_mma_kernel<<<gqk, 256>>>(qkv + 1 * QKV_N, qkv + 3 * QKV_N, attp + ATT_N);  // q_l, k_g

    softmax_kernel<<<2048, 256>>>(attp);
    softmax_kernel<<<2048, 256>>>(attp + ATT_N);

    dim3 gav(4, 32);
    av_mma_kernel<<<gav, 256>>>(attp,         qkv + 2 * QKV_N, yb);           // y_g
    av_mma_kernel<<<gav, 256>>>(attp + ATT_N, qkv + 5 * QKV_N, yb + QKV_N);   // y_l

    dim3 gproj(8, 4, 4);
    proj_mma_kernel<<<gproj, 256>>>(yb + QKV_N, Wp1, x_l, rw, out_l);
    proj_mma_kernel<<<gproj, 256>>>(yb,         Wp2, x_g, rw, out_g);
}